// round 6
// baseline (speedup 1.0000x reference)
#include <cuda_runtime.h>
#include <cuda_bf16.h>
#include <cstdint>

#define D_MODEL 1024
#define NUM_T   2048
#define BATCH   32

#define PE_ELEMS (NUM_T * D_MODEL)            // 2,097,152
#define PE_VEC4  (PE_ELEMS / 4)               // 524,288 = 2^19
#define DVEC     (D_MODEL / 4)                // 256

#define BPT     4                             // batches per task
#define GROUPS  (BATCH / BPT)                 // 8
#define NTASKS  ((unsigned)(PE_VEC4 * GROUPS))   // 4,194,304 = 2^22

#define NBLOCKS 1216                          // ~8 resident blocks x 152 SMs
#define NTHREADS (NBLOCKS * 256)

#define LOG2_10000 13.287712379549449f

// Persistent fused PE+add: single wave, grid-stride over 2^22 tasks.
// Task gidx -> pos = gidx & (2^19-1) (contiguous across concurrent threads),
// group = gidx >> 19 (8 groups of 4 batches). Eliminates ~13 wave
// transitions of the 16384-block version; memory pattern identical to R5.
__global__ void __launch_bounds__(256) fused_pe_add_kernel(const float4* __restrict__ x,
                                                           float4* __restrict__ out) {
    const float k = -2.0f / (float)D_MODEL * LOG2_10000;  // 10000^(-2i/D)=2^(ik)
    const unsigned tid0 = blockIdx.x * 256u + threadIdx.x;

    for (unsigned gidx = tid0; gidx < NTASKS; gidx += (unsigned)NTHREADS) {
        const unsigned pos = gidx & (PE_VEC4 - 1u);       // 0..2^19-1
        const unsigned g   = gidx >> 19;                  // 0..7

        const int t  = pos >> 8;                          // timestep
        const int i0 = (pos & (DVEC - 1)) * 4;            // first column (even)
        const float ft = (float)t;

        float4 pe;
        pe.x = sinf(ft * exp2f((float)(i0 + 0) * k));     // even i -> sin
        pe.y = cosf(ft * exp2f((float)(i0 + 1) * k));     // odd  i -> cos
        pe.z = sinf(ft * exp2f((float)(i0 + 2) * k));
        pe.w = cosf(ft * exp2f((float)(i0 + 3) * k));

        const unsigned base = pos + g * (unsigned)(BPT * PE_VEC4);

        float4 xv[BPT];
        #pragma unroll
        for (int b = 0; b < BPT; b++)
            xv[b] = __ldcs(&x[base + (unsigned)b * PE_VEC4]);

        #pragma unroll
        for (int b = 0; b < BPT; b++) {
            float4 o;
            o.x = xv[b].x + pe.x;
            o.y = xv[b].y + pe.y;
            o.z = xv[b].z + pe.z;
            o.w = xv[b].w + pe.w;
            __stcs(&out[base + (unsigned)b * PE_VEC4], o);
        }
    }
}

extern "C" void kernel_launch(void* const* d_in, const int* in_sizes, int n_in,
                              void* d_out, int out_size) {
    const float4* x = (const float4*)d_in[0];
    float4* out = (float4*)d_out;
    fused_pe_add_kernel<<<NBLOCKS, 256>>>(x, out);
}

// round 7
// speedup vs baseline: 1.1303x; 1.1303x over previous
#include <cuda_runtime.h>
#include <cuda_bf16.h>
#include <cstdint>

#define D_MODEL 1024
#define NUM_T   2048
#define BATCH   32

#define PE_ELEMS (NUM_T * D_MODEL)            // 2,097,152
#define PE_VEC8  (PE_ELEMS / 8)               // 262,144 = 2^18
#define DVEC8    (D_MODEL / 8)                // 128

#define BPT     2                             // batches per thread
#define GROUPS  (BATCH / BPT)                 // 16 block-groups

#define LOG2_10000 13.287712379549449f

// Blackwell 256-bit global load/store (sm_100+, PTX ISA 8.8)
__device__ __forceinline__ void ldg256_cs(const float* p, float* r) {
    asm volatile("ld.global.cs.v8.f32 {%0,%1,%2,%3,%4,%5,%6,%7}, [%8];"
                 : "=f"(r[0]), "=f"(r[1]), "=f"(r[2]), "=f"(r[3]),
                   "=f"(r[4]), "=f"(r[5]), "=f"(r[6]), "=f"(r[7])
                 : "l"(p));
}
__device__ __forceinline__ void stg256_cs(float* p, const float* r) {
    asm volatile("st.global.cs.v8.f32 [%0], {%1,%2,%3,%4,%5,%6,%7,%8};"
                 :: "l"(p),
                    "f"(r[0]), "f"(r[1]), "f"(r[2]), "f"(r[3]),
                    "f"(r[4]), "f"(r[5]), "f"(r[6]), "f"(r[7])
                 : "memory");
}

// Fused PE+add, 256-bit accesses. One thread = one (t, d-vec8) x 2 batches.
// Flat one-task-per-thread grid (persistent loop regressed in R6).
__global__ void __launch_bounds__(256) fused_pe_add_kernel(const float* __restrict__ x,
                                                           float* __restrict__ out) {
    const unsigned g   = blockIdx.x & (GROUPS - 1u);      // batch group 0..15
    const unsigned pb  = blockIdx.x >> 4;                 // position block 0..1023
    const unsigned pos = pb * 256u + threadIdx.x;         // 0..PE_VEC8-1

    const int t  = pos >> 7;                  // timestep 0..2047
    const int i0 = (int)(pos & (DVEC8 - 1u)) * 8;         // first column (even)
    const float ft = (float)t;

    // 10000^(-2*i/D) = 2^(i*k)
    const float k = -2.0f / (float)D_MODEL * LOG2_10000;
    float pe[8];
    #pragma unroll
    for (int j = 0; j < 8; j += 2) {
        pe[j]     = sinf(ft * exp2f((float)(i0 + j)     * k));  // even -> sin
        pe[j + 1] = cosf(ft * exp2f((float)(i0 + j + 1) * k));  // odd  -> cos
    }

    const unsigned base = (pos + g * (unsigned)(BPT * PE_VEC8)) * 8u;  // float index

    float xv[BPT][8];
    #pragma unroll
    for (int b = 0; b < BPT; b++)
        ldg256_cs(x + base + (unsigned)b * (PE_VEC8 * 8u), xv[b]);

    #pragma unroll
    for (int b = 0; b < BPT; b++) {
        float o[8];
        #pragma unroll
        for (int j = 0; j < 8; j++) o[j] = xv[b][j] + pe[j];
        stg256_cs(out + base + (unsigned)b * (PE_VEC8 * 8u), o);
    }
}

extern "C" void kernel_launch(void* const* d_in, const int* in_sizes, int n_in,
                              void* d_out, int out_size) {
    const float* x = (const float*)d_in[0];
    float* out = (float*)d_out;
    // (2^18 / 256) position blocks x 16 groups = 16384 blocks, exact cover
    fused_pe_add_kernel<<<(PE_VEC8 / 256) * GROUPS, 256>>>(x, out);
}

// round 8
// speedup vs baseline: 1.1386x; 1.0074x over previous
#include <cuda_runtime.h>
#include <cuda_bf16.h>
#include <cstdint>

#define D_MODEL 1024
#define NUM_T   2048
#define BATCH   32

#define PE_ELEMS (NUM_T * D_MODEL)            // 2,097,152
#define PE_VEC4  (PE_ELEMS / 4)               // 524,288 = 2^19
#define DVEC     (D_MODEL / 4)                // 256

#define BPT     4                             // batches per thread
#define GROUPS  (BATCH / BPT)                 // 8 block-groups

#define LOG2_10000 13.287712379549449f

// Fused PE+add (round-5 shape: the 76.4us plateau config) with cache-policy
// tweak: loads via ld.global.cg (L2-only; L1 gives zero reuse), stores with
// DEFAULT policy (let L2 aggregate writebacks instead of .cs evict-first).
__global__ void __launch_bounds__(256) fused_pe_add_kernel(const float4* __restrict__ x,
                                                           float4* __restrict__ out) {
    const unsigned g   = blockIdx.x & (GROUPS - 1u);      // batch group 0..7
    const unsigned pb  = blockIdx.x >> 3;                 // position block 0..2047
    const unsigned pos = pb * 256u + threadIdx.x;         // 0..PE_VEC4-1

    const int t  = pos >> 8;                  // timestep 0..2047
    const int i0 = (int)(pos & (DVEC - 1u)) * 4;          // first column (even)
    const float ft = (float)t;

    // 10000^(-2*i/D) = 2^(i*k)
    const float k = -2.0f / (float)D_MODEL * LOG2_10000;
    float4 pe;
    pe.x = sinf(ft * exp2f((float)(i0 + 0) * k));   // even i -> sin
    pe.y = cosf(ft * exp2f((float)(i0 + 1) * k));   // odd  i -> cos
    pe.z = sinf(ft * exp2f((float)(i0 + 2) * k));
    pe.w = cosf(ft * exp2f((float)(i0 + 3) * k));

    const unsigned base = pos + g * (unsigned)(BPT * PE_VEC4);

    float4 xv[BPT];
    #pragma unroll
    for (int b = 0; b < BPT; b++)
        xv[b] = __ldcg(&x[base + (unsigned)b * PE_VEC4]);   // L2-only load

    #pragma unroll
    for (int b = 0; b < BPT; b++) {
        float4 o;
        o.x = xv[b].x + pe.x;
        o.y = xv[b].y + pe.y;
        o.z = xv[b].z + pe.z;
        o.w = xv[b].w + pe.w;
        out[base + (unsigned)b * PE_VEC4] = o;              // default store policy
    }
}

extern "C" void kernel_launch(void* const* d_in, const int* in_sizes, int n_in,
                              void* d_out, int out_size) {
    const float4* x = (const float4*)d_in[0];
    float4* out = (float4*)d_out;
    // 16384 blocks x 256 threads, exact cover
    fused_pe_add_kernel<<<(PE_VEC4 / 256) * GROUPS, 256>>>(x, out);
}